// round 17
// baseline (speedup 1.0000x reference)
#include <cuda_runtime.h>
#include <cuda_fp16.h>
#include <math.h>
#include <stdint.h>

#define NIMG 800
typedef unsigned long long u64;

// ---------------- scratch ----------------
__device__ float g_pool1[(size_t)NIMG * 1764 * 64];
__device__ float g_pool2[(size_t)NIMG * 441 * 64];
__device__ float g_pool3[(size_t)NIMG * 100 * 64];
__device__ float g_pool4[(size_t)NIMG * 25 * 64];
__device__ float g_partA[(size_t)NIMG * 128];
__device__ float g_partB[(size_t)NIMG * 128];
__device__ float g_Z[2 * NIMG * 128];
__device__ float g_outs[5 * 21 * 32 * 64];
__device__ uint4 g_wh[3 * 4608];   // fp16 weights, pair-permuted B layout

// ---------------- warp mma (fp16 in, f32 acc) ----------------
__device__ __forceinline__ void mma16816(float* d, uint32_t a0, uint32_t a1,
                                         uint32_t a2, uint32_t a3,
                                         uint32_t b0, uint32_t b1) {
    asm volatile(
        "mma.sync.aligned.m16n8k16.row.col.f32.f16.f16.f32 "
        "{%0,%1,%2,%3}, {%4,%5,%6,%7}, {%8,%9}, {%0,%1,%2,%3};"
        : "+f"(d[0]), "+f"(d[1]), "+f"(d[2]), "+f"(d[3])
        : "r"(a0), "r"(a1), "r"(a2), "r"(a3), "r"(b0), "r"(b1));
}
__device__ __forceinline__ uint32_t packf2(float a, float b) {
    __half2 h = __floats2half2_rn(a, b);
    return *(uint32_t*)&h;
}

// ---------------- wconv: transpose + fp16 + pair-permute weights once ----------------
// word w (0..31) in a 64-ch row: kc=w>>3, v=w&7 -> c0 = kc*16 + (v>>1)*2 + (v&1)*8
__global__ void __launch_bounds__(256) wconv_kernel(
    const float* __restrict__ k2, const float* __restrict__ k3,
    const float* __restrict__ k4, uint4* __restrict__ wh)
{
    int idx = blockIdx.x * 256 + threadIdx.x;
    if (idx >= 3 * 4608) return;
    int layer = idx / 4608, rem = idx - layer * 4608;
    const float* w = (layer == 0) ? k2 : ((layer == 1) ? k3 : k4);
    int row = rem >> 3, ch = rem & 7;       // row = t*64 + oc
    int t = row >> 6, oc = row & 63;
    uint32_t out[4];
#pragma unroll
    for (int j = 0; j < 4; j++) {
        int wd = ch * 4 + j;
        int kc = wd >> 3, v = wd & 7;
        int c0 = kc * 16 + (v >> 1) * 2 + (v & 1) * 8;
        out[j] = packf2(w[t * 4096 + c0 * 64 + oc], w[t * 4096 + (c0 + 1) * 64 + oc]);
    }
    wh[idx] = *(uint4*)out;
}

// ================= conv1mma2: layer 1 (B permuted, LDS.64) =================
__global__ void __launch_bounds__(512) conv1mma2_kernel(
    const float* __restrict__ xs, const float* __restrict__ xq,
    const float* __restrict__ w, const float* __restrict__ bias,
    float* __restrict__ pool1, float* __restrict__ part)
{
    constexpr int WP = 86, P = WP * WP;
    constexpr int PENT = 96 + P + 96;
    constexpr int AR = 160;
    constexpr int OFF_P   = 1024;
    constexpr int OFF_B   = OFF_P + PENT * 12;
    constexpr int OFF_RAW = OFF_B + 64 * AR;

    extern __shared__ __align__(16) char smem[];
    int tid = threadIdx.x;
    int g = blockIdx.x;
    float* bias_sh = (float*)(smem + 16);
    if (tid < 64) bias_sh[tid] = bias[tid];

    {
        int b = g & 31, slot = g >> 5;
        const float* src = (slot < 20)
            ? (xs + (size_t)(b * 20 + slot) * 84 * 84 * 3)
            : (xq + (size_t)(b * 5 + (slot - 20)) * 84 * 84 * 3);
        float* Pp = (float*)(smem + OFF_P);
        for (int i = tid; i < PENT * 3; i += 512) {
            int sp = i / 3 - 96;
            int c = i - (sp + 96) * 3;
            float v = 0.f;
            if (sp >= 0 && sp < P) {
                int py = sp / WP, px = sp - py * WP;
                if (px >= 1 && px <= 84 && py >= 1 && py <= 84)
                    v = src[(size_t)((py - 1) * 84 + (px - 1)) * 3 + c];
            }
            Pp[i] = v;
        }
    }
    // B permuted: channel k -> byte (k>>4)*32 + (k&6)*4 + (k&1)*2 + ((k>>3)&1)*4
    for (int i = tid; i < 64 * 32; i += 512) {
        int oc = i >> 5, k = i & 31;
        float v = (k < 27) ? w[k * 64 + oc] : 0.f;
        int kl = k & 15;
        int boff = (k >> 4) * 32 + (kl & 6) * 4 + (kl & 1) * 2 + ((kl >> 3) & 1) * 4;
        *(__half*)(smem + OFF_B + oc * AR + boff) = __float2half_rn(v);
    }
    __syncthreads();

    int warp = tid >> 5, lane = tid & 31;
    int g_row = lane >> 2, four = lane & 3;
    int nmt = (warp < 6) ? 2 : 1;

    int rel[8];
#pragma unroll
    for (int kc = 0; kc < 2; kc++)
#pragma unroll
        for (int kh = 0; kh < 2; kh++)
#pragma unroll
            for (int h = 0; h < 2; h++) {
                int k = kc * 16 + kh * 8 + four * 2 + h;
                int t = k / 3, c = k - 3 * t;
                int shift = (t / 3 - 1) * WP + (t % 3 - 1);
                rel[kc * 4 + kh * 2 + h] = shift * 3 + c;
            }

    const float* Pimg = (float*)(smem + OFF_P) + 96 * 3;
    float* rawp = (float*)(smem + OFF_RAW);

    float ps[8][2], qs[8][2];
#pragma unroll
    for (int nt = 0; nt < 8; nt++) { ps[nt][0]=0.f; ps[nt][1]=0.f; qs[nt][0]=0.f; qs[nt][1]=0.f; }

    for (int yp2 = 0; yp2 < 21; yp2++) {
        int s0 = (4 * yp2 + 1) * WP;
        float d[2][8][4];
#pragma unroll
        for (int im = 0; im < 2; im++)
#pragma unroll
            for (int nt = 0; nt < 8; nt++)
#pragma unroll
                for (int i = 0; i < 4; i++) d[im][nt][i] = 0.f;

#pragma unroll
        for (int kc = 0; kc < 2; kc++)
#pragma unroll
            for (int im = 0; im < 2; im++) {
                if (im >= nmt) break;
                int mt = warp + im * 16;
                uint32_t ah[4], al[4];
#pragma unroll
                for (int r = 0; r < 4; r++) {
                    int row = mt * 16 + g_row + (r & 1) * 8;
                    int base = (s0 + row) * 3;
                    int kh = r >> 1;
                    float v0 = Pimg[base + rel[kc * 4 + kh * 2 + 0]];
                    float v1 = Pimg[base + rel[kc * 4 + kh * 2 + 1]];
                    uint32_t hh = packf2(v0, v1);
                    float2 hb = __half22float2(*(__half2*)&hh);
                    al[r] = packf2(v0 - hb.x, v1 - hb.y);
                    ah[r] = hh;
                }
#pragma unroll
                for (int nt = 0; nt < 8; nt++) {
                    uint2 bu = *(const uint2*)(smem + OFF_B + (nt * 8 + g_row) * AR
                                               + kc * 32 + four * 8);
                    mma16816(d[im][nt], ah[0], ah[1], ah[2], ah[3], bu.x, bu.y);
                    mma16816(d[im][nt], al[0], al[1], al[2], al[3], bu.x, bu.y);
                }
            }

#pragma unroll
        for (int im = 0; im < 2; im++) {
            if (im >= nmt) break;
            int mt = warp + im * 16;
#pragma unroll
            for (int rr = 0; rr < 2; rr++) {
                int m = mt * 16 + g_row + rr * 8;
                bool stat = false;
                if (m < 344) {
                    int px = m % WP;
                    stat = (px >= 1 && px <= 84);
                }
#pragma unroll
                for (int nt = 0; nt < 8; nt++) {
                    int oc = nt * 8 + four * 2;
                    float vx = d[im][nt][rr * 2]     + bias_sh[oc];
                    float vy = d[im][nt][rr * 2 + 1] + bias_sh[oc + 1];
                    *(float2*)(rawp + m * 64 + oc) = make_float2(vx, vy);
                    if (stat) {
                        ps[nt][0] += vx; qs[nt][0] += vx * vx;
                        ps[nt][1] += vy; qs[nt][1] += vy * vy;
                    }
                }
            }
        }
        __syncthreads();
        for (int i = tid; i < 2 * 42 * 64; i += 512) {
            int lpr = i / (42 * 64);
            int rest = i - lpr * (42 * 64);
            int ox = rest >> 6, c = rest & 63;
            int m0 = lpr * 172 + 2 * ox + 1;
            float v = fmaxf(fmaxf(rawp[m0 * 64 + c], rawp[(m0 + 1) * 64 + c]),
                            fmaxf(rawp[(m0 + WP) * 64 + c], rawp[(m0 + WP + 1) * 64 + c]));
            pool1[((size_t)g * 1764 + (2 * yp2 + lpr) * 42 + ox) * 64 + c] = v;
        }
        __syncthreads();
    }

#pragma unroll
    for (int nt = 0; nt < 8; nt++)
#pragma unroll
        for (int j = 0; j < 2; j++) {
#pragma unroll
            for (int off = 16; off >= 4; off >>= 1) {
                ps[nt][j] += __shfl_down_sync(~0u, ps[nt][j], off);
                qs[nt][j] += __shfl_down_sync(~0u, qs[nt][j], off);
            }
        }
    float* wst = rawp;
    if (lane < 4) {
#pragma unroll
        for (int nt = 0; nt < 8; nt++)
#pragma unroll
            for (int j = 0; j < 2; j++) {
                int oc = nt * 8 + lane * 2 + j;
                wst[warp * 128 + oc]      = ps[nt][j];
                wst[warp * 128 + 64 + oc] = qs[nt][j];
            }
    }
    __syncthreads();
    if (tid < 128) {
        float s = 0.f;
#pragma unroll
        for (int wi = 0; wi < 16; wi++) s += wst[wi * 128 + tid];
        part[(size_t)g * 128 + tid] = s;
    }
}

// ================= mmaconv: L2-4, pair-permuted staging + LDS.64 fragments =================
template <int NX, int TR, int NT, int IMGS>
__global__ void __launch_bounds__(512) mmaconv_kernel(
    const float* __restrict__ in, const float* __restrict__ partin,
    const float* __restrict__ gamma, const float* __restrict__ beta, float invPrev,
    const uint4* __restrict__ whl, const float* __restrict__ bias,
    float* __restrict__ pooled, float* __restrict__ partout)
{
    constexpr int W = NX + 2, PIX = NX * NX, Np = NX / 2;
    constexpr int SROWS = (TR + 4) * W;
    constexpr int SROW = 160;                // 40 words == 8 mod 32: LDS.64 conflict-free
    constexpr int BTAP = 64 * SROW;
    constexpr int OFF_B  = 1024;
    constexpr int OFF_SH = OFF_B + 9 * BTAP;
    constexpr int OFF_SL = OFF_SH + SROWS * SROW;

    extern __shared__ __align__(16) char smem[];
    int tid = threadIdx.x;
    int g0 = blockIdx.x * IMGS, slot = g0 >> 5;
    float* bias_sh = (float*)(smem + 16);
    float* ab_sh   = (float*)(smem + 304);
    if (tid < 64) bias_sh[tid] = bias[tid];
    if (tid >= 64 && tid < 128) {
        int c = tid - 64;
        float s = 0.f, q = 0.f;
        for (int b = 0; b < 32; b++) {
            s += partin[(size_t)(slot * 32 + b) * 128 + c];
            q += partin[(size_t)(slot * 32 + b) * 128 + 64 + c];
        }
        float mn = s * invPrev;
        float var = q * invPrev - mn * mn;
        float sc = gamma[c] * rsqrtf(var + 1e-3f);
        ab_sh[c * 2] = sc;
        ab_sh[c * 2 + 1] = beta[c] - mn * sc;
    }
    for (int i = tid; i < 4608; i += 512) {
        int row = i >> 3, ch = i & 7;
        *(uint4*)(smem + OFF_B + row * SROW + ch * 16) = whl[i];
    }

    int warp = tid >> 5, lane = tid & 31;
    int g_row = lane >> 2, four = lane & 3;
    float* rawp = (float*)(smem + OFF_SH);

    for (int img = 0; img < IMGS; img++) {
        int g = g0 + img;
        float ps[8][2], qs[8][2];
#pragma unroll
        for (int nt = 0; nt < 8; nt++) { ps[nt][0]=0.f; ps[nt][1]=0.f; qs[nt][0]=0.f; qs[nt][1]=0.f; }

        for (int tile = 0; tile < NT; tile++) {
            int r0 = tile * TR;
            int rows = (NX - r0 < TR) ? (NX - r0) : TR;
            int pxc = rows * NX;
            int mtiles = (pxc + 15) >> 4;
            bool vw = warp < mtiles;

            __syncthreads();
            int nstrip = (rows + 2) * W;
            for (int i = tid; i < nstrip * 16; i += 512) {
                int s = i >> 4, c4 = (i & 15) * 4;
                int p = r0 + s / W, px = s % W;
                float4 v = make_float4(0.f, 0.f, 0.f, 0.f);
                if (px >= 1 && px <= NX && p >= 1 && p <= NX) {
                    float4 rv = *(const float4*)&in[((size_t)g * PIX + (p - 1) * NX + (px - 1)) * 64 + c4];
                    v.x = fmaxf(fmaf(ab_sh[(c4 + 0) * 2], rv.x, ab_sh[(c4 + 0) * 2 + 1]), 0.f);
                    v.y = fmaxf(fmaf(ab_sh[(c4 + 1) * 2], rv.y, ab_sh[(c4 + 1) * 2 + 1]), 0.f);
                    v.z = fmaxf(fmaf(ab_sh[(c4 + 2) * 2], rv.z, ab_sh[(c4 + 2) * 2 + 1]), 0.f);
                    v.w = fmaxf(fmaf(ab_sh[(c4 + 3) * 2], rv.w, ab_sh[(c4 + 3) * 2 + 1]), 0.f);
                }
                uint32_t hx = packf2(v.x, v.y), hz = packf2(v.z, v.w);
                float2 bx = __half22float2(*(__half2*)&hx);
                float2 bz = __half22float2(*(__half2*)&hz);
                // permuted store: c4 pair -> block (c4>>4)*32, g0 = ((c4&4)<<2)+((c4&8)>>1)
                int boff = s * SROW + (c4 >> 4) * 32 + ((c4 & 4) << 2) + ((c4 & 8) >> 1);
                *(uint32_t*)(smem + OFF_SH + boff)     = hx;
                *(uint32_t*)(smem + OFF_SH + boff + 8) = hz;
                *(uint32_t*)(smem + OFF_SL + boff)     = packf2(v.x - bx.x, v.y - bx.y);
                *(uint32_t*)(smem + OFF_SL + boff + 8) = packf2(v.z - bz.x, v.w - bz.y);
            }
            __syncthreads();

            int rA[2] = {0, 0};
            if (vw) {
#pragma unroll
                for (int h = 0; h < 2; h++) {
                    int ml = warp * 16 + h * 8 + g_row;
                    rA[h] = (ml / NX) * W + (ml % NX);
                }
            }

            float d[8][4];
#pragma unroll
            for (int nt = 0; nt < 8; nt++)
#pragma unroll
                for (int i = 0; i < 4; i++) d[nt][i] = 0.f;

#pragma unroll 1
            for (int t = 0; t < 9; t++) {
                int rshift = (t / 3) * W + (t % 3);
                const char* bt = smem + OFF_B + t * BTAP;
#pragma unroll
                for (int kc = 0; kc < 4; kc++) {
                    int cb8 = kc * 32 + four * 8;
                    if (vw) {
                        uint2 au0 = *(const uint2*)(smem + OFF_SH + (rA[0] + rshift) * SROW + cb8);
                        uint2 au1 = *(const uint2*)(smem + OFF_SH + (rA[1] + rshift) * SROW + cb8);
                        uint2 al0 = *(const uint2*)(smem + OFF_SL + (rA[0] + rshift) * SROW + cb8);
                        uint2 al1 = *(const uint2*)(smem + OFF_SL + (rA[1] + rshift) * SROW + cb8);
#pragma unroll
                        for (int nt = 0; nt < 8; nt++) {
                            uint2 bu = *(const uint2*)(bt + (nt * 8 + g_row) * SROW + cb8);
                            mma16816(d[nt], au0.x, au1.x, au0.y, au1.y, bu.x, bu.y);
                            mma16816(d[nt], al0.x, al1.x, al0.y, al1.y, bu.x, bu.y);
                        }
                    }
                }
            }
            __syncthreads();

            if (vw) {
#pragma unroll
                for (int rr = 0; rr < 2; rr++) {
                    int ml = warp * 16 + g_row + rr * 8;
                    if (ml < pxc) {
#pragma unroll
                        for (int nt = 0; nt < 8; nt++) {
                            int oc = nt * 8 + four * 2;
                            float vx = d[nt][rr * 2]     + bias_sh[oc];
                            float vy = d[nt][rr * 2 + 1] + bias_sh[oc + 1];
                            *(float2*)(rawp + ml * 64 + oc) = make_float2(vx, vy);
                            ps[nt][0] += vx; qs[nt][0] += vx * vx;
                            ps[nt][1] += vy; qs[nt][1] += vy * vy;
                        }
                    }
                }
            }
            __syncthreads();

            int pr0 = r0 >> 1;
            int rend = r0 + rows; if (rend > 2 * Np) rend = 2 * Np;
            int prn = (rend >> 1) - pr0;
            for (int i = tid; i < prn * Np * 64; i += 512) {
                int lpr = i / (Np * 64);
                int rest = i - lpr * (Np * 64);
                int ox = rest >> 6, c = rest & 63;
                int base = ((2 * lpr) * NX + 2 * ox) * 64 + c;
                float v = fmaxf(fmaxf(rawp[base], rawp[base + 64]),
                                fmaxf(rawp[base + NX * 64], rawp[base + NX * 64 + 64]));
                pooled[((size_t)g * (Np * Np) + (pr0 + lpr) * Np + ox) * 64 + c] = v;
            }
        }

#pragma unroll
        for (int nt = 0; nt < 8; nt++)
#pragma unroll
            for (int j = 0; j < 2; j++) {
#pragma unroll
                for (int off = 16; off >= 4; off >>= 1) {
                    ps[nt][j] += __shfl_down_sync(~0u, ps[nt][j], off);
                    qs[nt][j] += __shfl_down_sync(~0u, qs[nt][j], off);
                }
            }
        __syncthreads();
        float* wst = (float*)(smem + OFF_SH);
        if (lane < 4) {
#pragma unroll
            for (int nt = 0; nt < 8; nt++)
#pragma unroll
                for (int j = 0; j < 2; j++) {
                    int oc = nt * 8 + lane * 2 + j;
                    wst[warp * 128 + oc]      = ps[nt][j];
                    wst[warp * 128 + 64 + oc] = qs[nt][j];
                }
        }
        __syncthreads();
        if (tid < 128) {
            float s = 0.f;
#pragma unroll
            for (int wi = 0; wi < 16; wi++) s += wst[wi * 128 + tid];
            partout[(size_t)g * 128 + tid] = s;
        }
    }
}

// ---------------- gemmz: fused BN4 affine prologue ----------------
__global__ void __launch_bounds__(256) gemmz_kernel(
    const float* __restrict__ emb, const float* __restrict__ partin,
    const float* __restrict__ gamma, const float* __restrict__ beta, float invPrev,
    const float* __restrict__ fk, const float* __restrict__ fb,
    const float* __restrict__ bk, const float* __restrict__ bb,
    float* __restrict__ Z)
{
    int gb = blockIdx.x, dir = blockIdx.y;
    const float* W = dir ? bk : fk;
    const float* bias = dir ? bb : fb;
    float* Zo = Z + (size_t)dir * NIMG * 128;
    __shared__ float A_sh[32][33];
    __shared__ __align__(16) float B_sh[32][128];
    __shared__ float ab_sh[128];
    int tid = threadIdx.x, jj = tid & 31, gg = tid >> 5;
    if (tid < 64) {
        float s = 0.f, q = 0.f;
        for (int b = 0; b < 32; b++) {
            s += partin[(size_t)(gb * 32 + b) * 128 + tid];
            q += partin[(size_t)(gb * 32 + b) * 128 + 64 + tid];
        }
        float mn = s * invPrev;
        float var = q * invPrev - mn * mn;
        float sc = gamma[tid] * rsqrtf(var + 1e-3f);
        ab_sh[tid * 2] = sc;
        ab_sh[tid * 2 + 1] = beta[tid] - mn * sc;
    }
    __syncthreads();
    float acc[4][4] = {};
    for (int d0 = 0; d0 < 1600; d0 += 32) {
        for (int i = tid; i < 1024; i += 256) {
            int r = i >> 5, dd = i & 31, d = d0 + dd, c = d & 63;
            float raw = emb[(size_t)(gb * 32 + r) * 1600 + d];
            A_sh[r][dd] = fmaxf(fmaf(ab_sh[c * 2], raw, ab_sh[c * 2 + 1]), 0.f);
        }
        for (int i = tid; i < 4096; i += 256)
            B_sh[i >> 7][i & 127] = W[(size_t)(d0 + (i >> 7)) * 128 + (i & 127)];
        __syncthreads();
#pragma unroll
        for (int dd = 0; dd < 32; dd++) {
            float4 bv = *(const float4*)&B_sh[dd][jj * 4];
#pragma unroll
            for (int r = 0; r < 4; r++) {
                float a = A_sh[gg * 4 + r][dd];
                acc[r][0] += a * bv.x; acc[r][1] += a * bv.y;
                acc[r][2] += a * bv.z; acc[r][3] += a * bv.w;
            }
        }
        __syncthreads();
    }
#pragma unroll
    for (int r = 0; r < 4; r++)
#pragma unroll
        for (int c = 0; c < 4; c++)
            Zo[(size_t)(gb * 32 + gg * 4 + r) * 128 + jj * 4 + c] = acc[r][c] + bias[jj * 4 + c];
}

// ---------------- LSTM ----------------
__global__ void __launch_bounds__(672) lstm_kernel(
    const float* __restrict__ Z,
    const float* __restrict__ fr, const float* __restrict__ br,
    float* __restrict__ outs)
{
    int q = blockIdx.x, dir = blockIdx.y;
    const float* R = dir ? br : fr;
    const float* Zp = Z + (size_t)dir * NIMG * 128;
    __shared__ float Wh[32][128];
    __shared__ float h_sh[21][32], c_sh[21][32];
    int tid = threadIdx.x;
    for (int i = tid; i < 4096; i += 672) Wh[i >> 7][i & 127] = R[i];
    int p = tid >> 5, j = tid & 31;
    h_sh[p][j] = 0.f; c_sh[p][j] = 0.f;
    __syncthreads();
    int slot = (p < 20) ? p : (20 + q);
    for (int step = 0; step < 32; step++) {
        int t = dir ? (31 - step) : step;
        const float* zr = Zp + (size_t)(slot * 32 + t) * 128;
        float z0 = zr[j], z1 = zr[32 + j], z2 = zr[64 + j], z3 = zr[96 + j];
#pragma unroll
        for (int k = 0; k < 32; k++) {
            float hk = h_sh[p][k];
            z0 += hk * Wh[k][j]; z1 += hk * Wh[k][32 + j];
            z2 += hk * Wh[k][64 + j]; z3 += hk * Wh[k][96 + j];
        }
        float ig = 1.f / (1.f + expf(-z0)), fg = 1.f / (1.f + expf(-z1));
        float gg = tanhf(z2), og = 1.f / (1.f + expf(-z3));
        float cn = fg * c_sh[p][j] + ig * gg;
        float hn = og * tanhf(cn);
        __syncthreads();
        h_sh[p][j] = hn; c_sh[p][j] = cn;
        outs[(size_t)((q * 21 + p) * 32 + t) * 64 + dir * 32 + j] = hn;
        __syncthreads();
    }
}

// ---------------- attention + CE + acc ----------------
__global__ void __launch_bounds__(256) final_kernel(
    const float* __restrict__ outs,
    const int* __restrict__ ysup, const int* __restrict__ yqry,
    float* __restrict__ out)
{
    __shared__ float ce_sh[160], eq_sh[160];
    int tid = threadIdx.x;
    if (tid < 160) {
        int q = tid / 32, b = tid % 32;
        const float* qry = outs + (size_t)((q * 21 + 20) * 32 + b) * 64;
        float logit[20];
        for (int s = 0; s < 20; s++) {
            const float* sp = outs + (size_t)((q * 21 + s) * 32 + b) * 64;
            float d = 0.f, n2 = 0.f;
            for (int k = 0; k < 64; k++) { d += qry[k] * sp[k]; n2 += sp[k] * sp[k]; }
            logit[s] = d * rsqrtf(fmaxf(n2, 1e-10f));
        }
        float mx = logit[0];
        for (int s = 1; s < 20; s++) mx = fmaxf(mx, logit[s]);
        float den = 0.f;
        for (int s = 0; s < 20; s++) { logit[s] = expf(logit[s] - mx); den += logit[s]; }
        float invden = 1.f / den;
        float preds[20];
        for (int wq = 0; wq < 20; wq++) preds[wq] = 0.f;
        for (int s = 0; s < 20; s++) preds[ysup[b * 20 + s]] += logit[s] * invden;
        int yq = yqry[b * 5 + q];
        float pv = fminf(fmaxf(preds[yq], 1e-7f), 1.f - 1e-7f);
        ce_sh[tid] = -logf(pv);
        int best = 0;
        for (int wq = 1; wq < 20; wq++) if (preds[wq] > preds[best]) best = wq;
        eq_sh[tid] = (best == yq) ? 1.f : 0.f;
    }
    __syncthreads();
    if (tid < 32) {
        float s = 0.f;
        for (int q = 0; q < 5; q++) s += ce_sh[q * 32 + tid];
        out[tid] = s * 0.2f;
    }
    if (tid == 0) {
        float s = 0.f;
        for (int i = 0; i < 160; i++) s += eq_sh[i];
        out[32] = s / 160.f;
    }
}

// ---------------- launch ----------------
extern "C" void kernel_launch(void* const* d_in, const int* in_sizes, int n_in,
                              void* d_out, int out_size)
{
    (void)in_sizes; (void)n_in; (void)out_size;
    const float* xs = (const float*)d_in[0];
    const int* ysup = (const int*)d_in[1];
    const float* xq = (const float*)d_in[2];
    const int* yqry = (const int*)d_in[3];
    const float *k1=(const float*)d_in[4],  *b1=(const float*)d_in[5],  *g1=(const float*)d_in[6],  *be1=(const float*)d_in[7];
    const float *k2=(const float*)d_in[8],  *b2=(const float*)d_in[9],  *g2=(const float*)d_in[10], *be2=(const float*)d_in[11];
    const float *k3=(const float*)d_in[12], *b3=(const float*)d_in[13], *g3=(const float*)d_in[14], *be3=(const float*)d_in[15];
    const float *k4=(const float*)d_in[16], *b4=(const float*)d_in[17], *g4=(const float*)d_in[18], *be4=(const float*)d_in[19];
    const float *fk=(const float*)d_in[20], *fr=(const float*)d_in[21], *fb=(const float*)d_in[22];
    const float *bk=(const float*)d_in[23], *br=(const float*)d_in[24], *bb=(const float*)d_in[25];

    float *pool1, *pool2, *pool3, *pool4, *partA, *partB, *Z, *outs;
    uint4* wh;
    cudaGetSymbolAddress((void**)&pool1, g_pool1);
    cudaGetSymbolAddress((void**)&pool2, g_pool2);
    cudaGetSymbolAddress((void**)&pool3, g_pool3);
    cudaGetSymbolAddress((void**)&pool4, g_pool4);
    cudaGetSymbolAddress((void**)&partA, g_partA);
    cudaGetSymbolAddress((void**)&partB, g_partB);
    cudaGetSymbolAddress((void**)&Z, g_Z);
    cudaGetSymbolAddress((void**)&outs, g_outs);
    cudaGetSymbolAddress((void**)&wh, g_wh);

    const int SM1  = 1024 + 7588 * 12 + 64 * 160 + 352 * 64 * 4;         // 192432
    const int SM42 = 1024 + 9 * 64 * 160 + 2 * (8 * 44) * 160;           // 205824
    const int SM21 = 1024 + 9 * 64 * 160 + 2 * (16 * 23) * 160;          // 210944
    const int SM10 = 1024 + 9 * 64 * 160 + 2 * (14 * 12) * 160;          // 146944
    cudaFuncSetAttribute(conv1mma2_kernel,          cudaFuncAttributeMaxDynamicSharedMemorySize, SM1);
    cudaFuncSetAttribute(mmaconv_kernel<42,4,11,1>, cudaFuncAttributeMaxDynamicSharedMemorySize, SM42);
    cudaFuncSetAttribute(mmaconv_kernel<21,12,2,2>, cudaFuncAttributeMaxDynamicSharedMemorySize, SM21);
    cudaFuncSetAttribute(mmaconv_kernel<10,10,1,4>, cudaFuncAttributeMaxDynamicSharedMemorySize, SM10);

    wconv_kernel<<<(3 * 4608 + 255) / 256, 256>>>(k2, k3, k4, wh);
    // L1 -> pool1, partA
    conv1mma2_kernel<<<NIMG, 512, SM1>>>(xs, xq, k1, b1, pool1, partA);
    // L2 -> pool2, partB
    mmaconv_kernel<42,4,11,1><<<NIMG, 512, SM42>>>(pool1, partA, g1, be1, 1.f / (32.f * 7056.f),
                                                   wh, b2, pool2, partB);
    // L3 (2 imgs/block) -> pool3, partA
    mmaconv_kernel<21,12,2,2><<<NIMG / 2, 512, SM21>>>(pool2, partB, g2, be2, 1.f / (32.f * 1764.f),
                                                       wh + 4608, b3, pool3, partA);
    // L4 (4 imgs/block) -> pool4, partB
    mmaconv_kernel<10,10,1,4><<<NIMG / 4, 512, SM10>>>(pool3, partA, g3, be3, 1.f / (32.f * 441.f),
                                                       wh + 2 * 4608, b4, pool4, partB);
    // gemmz: BN4 from partB
    gemmz_kernel<<<dim3(25, 2), 256>>>(pool4, partB, g4, be4, 1.f / (32.f * 100.f),
                                       fk, fb, bk, bb, Z);
    lstm_kernel<<<dim3(5, 2), 672>>>(Z, fr, br, outs);
    final_kernel<<<1, 256>>>(outs, ysup, yqry, (float*)d_out);
}